// round 13
// baseline (speedup 1.0000x reference)
#include <cuda_runtime.h>
#include <cuda_fp16.h>
#include <mma.h>
#include <math.h>

using namespace nvcuda;

#define N_DRUG 20000
#define N_DIS  20000
#define NEDGE  300000
#define DIM    128

#define SCAN_ELEMS 1024
#define SCAN_NB    ((N_DIS + SCAN_ELEMS - 1) / SCAN_ELEMS)   // 20
#define OFF_STRIDE (N_DIS + 4)

#define GROWS 64
#define GBLKS ((N_DRUG + GROWS - 1) / GROWS)   // 313

#define HIST_MLP 4

// ---------------- scratch (device globals; no allocation allowed) ----------
__device__ __half g_Whh[3][N_DIS * DIM];     // fp16 Wh per etype (gather source)

__device__ float g_el_ind[N_DRUG];
__device__ float g_er_rev[N_DRUG];
__device__ float g_el_rev[N_DIS];
__device__ float g_er_ind[N_DIS];
__device__ float g_el_dd [N_DIS];
__device__ float g_er_dd [N_DIS];

__device__ int   g_deg[3][N_DIS];
__device__ int   g_off[3][OFF_STRIDE];
__device__ int   g_bsum[3][SCAN_NB];
__device__ int   g_rank[3][NEDGE];           // per-edge rank within its dst
__device__ int2  g_edge[3][NEDGE];           // packed (src, logit-bits), dst-sorted

// ---------------- param structs ---------------------------------------------
struct GemmArgs {
    const float* X[3];
    const float* W[3];
    const float* b[3];
    const float* a1[3];
    const float* a2[3];
    float* s1[3];
    float* s2[3];
};

struct EdgeIdx {
    const int* src[3];
    const int* dst[3];
};

// ---------------- helpers ----------------------------------------------------
__device__ __forceinline__ float leaky(float x) {
    return x > 0.0f ? x : 0.01f * x;
}

__device__ __forceinline__ void red_add_v4(float* addr, float4 v) {
    asm volatile("red.global.add.v4.f32 [%0], {%1,%2,%3,%4};"
                 :: "l"(addr), "f"(v.x), "f"(v.y), "f"(v.z), "f"(v.w)
                 : "memory");
}

// packed dual-FMA: acc(f32x2) += a(f32x2) * b(f32x2)
__device__ __forceinline__ void ffma2(unsigned long long& acc,
                                      unsigned long long a,
                                      unsigned long long b) {
    asm("fma.rn.f32x2 %0, %1, %2, %0;" : "+l"(acc) : "l"(a), "l"(b));
}

// ---------------- WMMA GEMM + bias + attention scalar projections ------------
__global__ void __launch_bounds__(128) gemm_wmma_kernel(GemmArgs ga) {
    const int t = blockIdx.y;
    const int row0 = blockIdx.x * GROWS;
    const float* __restrict__ X  = ga.X[t];
    const float* __restrict__ Wg = ga.W[t];

    __shared__ union {
        struct {
            __half Xs[GROWS][72];
            __half Ws[64][136];
        } mm;
        float ep[GROWS][132];
    } sm;

    int tid  = threadIdx.x;
    int warp = tid >> 5;
    int lane = tid & 31;

    wmma::fragment<wmma::accumulator, 16, 16, 16, float> acc[4][2];
    #pragma unroll
    for (int rt = 0; rt < 4; rt++)
        #pragma unroll
        for (int nf = 0; nf < 2; nf++)
            wmma::fill_fragment(acc[rt][nf], 0.0f);

    for (int chunk = 0; chunk < 2; chunk++) {
        __syncthreads();
        {
            int r  = tid >> 4;
            int cg = (tid & 15) * 4;
            #pragma unroll
            for (int rr = r; rr < GROWS; rr += 8) {
                int grow = row0 + rr;
                float4 x4 = make_float4(0.f, 0.f, 0.f, 0.f);
                if (grow < N_DRUG)
                    x4 = *(const float4*)&X[(size_t)grow * DIM + chunk * 64 + cg];
                *(__half2*)&sm.mm.Xs[rr][cg]     = __floats2half2_rn(x4.x, x4.y);
                *(__half2*)&sm.mm.Xs[rr][cg + 2] = __floats2half2_rn(x4.z, x4.w);
            }
        }
        {
            int r  = tid >> 4;
            int wc = (tid & 15) * 8;
            #pragma unroll
            for (int rr = r; rr < 64; rr += 8) {
                const float* wp = &Wg[(size_t)(chunk * 64 + rr) * DIM + wc];
                float4 f0 = *(const float4*)wp;
                float4 f1 = *(const float4*)(wp + 4);
                __half2 h0 = __floats2half2_rn(f0.x, f0.y);
                __half2 h1 = __floats2half2_rn(f0.z, f0.w);
                __half2 h2 = __floats2half2_rn(f1.x, f1.y);
                __half2 h3 = __floats2half2_rn(f1.z, f1.w);
                uint4 u;
                u.x = *(unsigned*)&h0; u.y = *(unsigned*)&h1;
                u.z = *(unsigned*)&h2; u.w = *(unsigned*)&h3;
                *(uint4*)&sm.mm.Ws[rr][wc] = u;
            }
        }
        __syncthreads();

        #pragma unroll
        for (int k2 = 0; k2 < 4; k2++) {
            wmma::fragment<wmma::matrix_b, 16, 16, 16, __half, wmma::row_major> b0, b1;
            wmma::load_matrix_sync(b0, &sm.mm.Ws[k2 * 16][warp * 32],      136);
            wmma::load_matrix_sync(b1, &sm.mm.Ws[k2 * 16][warp * 32 + 16], 136);
            #pragma unroll
            for (int rt = 0; rt < 4; rt++) {
                wmma::fragment<wmma::matrix_a, 16, 16, 16, __half, wmma::row_major> a;
                wmma::load_matrix_sync(a, &sm.mm.Xs[rt * 16][k2 * 16], 72);
                wmma::mma_sync(acc[rt][0], a, b0, acc[rt][0]);
                wmma::mma_sync(acc[rt][1], a, b1, acc[rt][1]);
            }
        }
    }

    __syncthreads();
    #pragma unroll
    for (int rt = 0; rt < 4; rt++) {
        wmma::store_matrix_sync(&sm.ep[rt * 16][warp * 32],      acc[rt][0], 132,
                                wmma::mem_row_major);
        wmma::store_matrix_sync(&sm.ep[rt * 16][warp * 32 + 16], acc[rt][1], 132,
                                wmma::mem_row_major);
    }
    __syncthreads();

    float4 b4  = *(const float4*)&ga.b[t][lane * 4];
    float4 a14 = *(const float4*)&ga.a1[t][lane * 4];
    float4 a24 = *(const float4*)&ga.a2[t][lane * 4];
    __half* __restrict__ Whh = g_Whh[t];

    #pragma unroll 4
    for (int r = 0; r < 16; r++) {
        int grow = row0 + warp * 16 + r;
        if (grow >= N_DRUG) break;
        float4 v = *(const float4*)&sm.ep[warp * 16 + r][lane * 4];
        v.x += b4.x; v.y += b4.y; v.z += b4.z; v.w += b4.w;

        __half2 h0 = __floats2half2_rn(v.x, v.y);
        __half2 h1 = __floats2half2_rn(v.z, v.w);
        uint2 u;
        u.x = *(unsigned*)&h0;
        u.y = *(unsigned*)&h1;
        *(uint2*)&Whh[(size_t)grow * DIM + lane * 4] = u;

        float p1 = v.x * a14.x + v.y * a14.y + v.z * a14.z + v.w * a14.w;
        float p2 = v.x * a24.x + v.y * a24.y + v.z * a24.z + v.w * a24.w;
        #pragma unroll
        for (int o = 16; o > 0; o >>= 1) {
            p1 += __shfl_down_sync(0xFFFFFFFFu, p1, o);
            p2 += __shfl_down_sync(0xFFFFFFFFu, p2, o);
        }
        if (lane == 0) { ga.s1[t][grow] = p1; ga.s2[t][grow] = p2; }
    }
}

// ---------------- histogram + rank capture, MLP=4 ---------------------------
__global__ void hist_kernel(EdgeIdx ei) {
    int t = blockIdx.y;
    const int* __restrict__ dst = ei.dst[t];
    int stride = gridDim.x * blockDim.x;
    int i0 = blockIdx.x * blockDim.x + threadIdx.x;

    int idx[HIST_MLP], d[HIST_MLP];
    #pragma unroll
    for (int k = 0; k < HIST_MLP; k++) {
        idx[k] = i0 + k * stride;
        d[k]   = (idx[k] < NEDGE) ? dst[idx[k]] : -1;
    }
    int r[HIST_MLP];
    #pragma unroll
    for (int k = 0; k < HIST_MLP; k++)
        if (d[k] >= 0) r[k] = atomicAdd(&g_deg[t][d[k]], 1);
    #pragma unroll
    for (int k = 0; k < HIST_MLP; k++)
        if (d[k] >= 0) g_rank[t][idx[k]] = r[k];
}

// ---------------- scan phase 1: per-block partial sums -----------------------
__global__ void __launch_bounds__(256) scan1_kernel() {
    int t   = blockIdx.y;
    int b   = blockIdx.x;
    int tid = threadIdx.x;
    int idx = b * SCAN_ELEMS + tid * 4;

    int4 v = (idx < N_DIS) ? *(const int4*)&g_deg[t][idx]
                           : make_int4(0, 0, 0, 0);
    int s = v.x + v.y + v.z + v.w;

    int lane = tid & 31, wid = tid >> 5;
    #pragma unroll
    for (int o = 16; o > 0; o >>= 1)
        s += __shfl_down_sync(0xFFFFFFFFu, s, o);

    __shared__ int ws[8];
    if (lane == 0) ws[wid] = s;
    __syncthreads();
    if (tid == 0) {
        int tot = 0;
        #pragma unroll
        for (int i = 0; i < 8; i++) tot += ws[i];
        g_bsum[t][b] = tot;
        if (b == 0) g_off[t][N_DIS] = NEDGE;
    }
}

// ---------------- scan phase 2: final offsets ---------------------------------
__global__ void __launch_bounds__(256) scan3_kernel() {
    int t   = blockIdx.y;
    int b   = blockIdx.x;
    int tid = threadIdx.x;
    int idx = b * SCAN_ELEMS + tid * 4;
    int lane = tid & 31, wid = tid >> 5;

    __shared__ int s_base;
    if (wid == 0) {
        int v = (lane < b && lane < SCAN_NB) ? g_bsum[t][lane] : 0;
        #pragma unroll
        for (int o = 16; o > 0; o >>= 1)
            v += __shfl_down_sync(0xFFFFFFFFu, v, o);
        if (lane == 0) s_base = v;
    }

    int4 v = (idx < N_DIS) ? *(const int4*)&g_deg[t][idx]
                           : make_int4(0, 0, 0, 0);
    int s = v.x + v.y + v.z + v.w;

    int x = s;
    #pragma unroll
    for (int o = 1; o < 32; o <<= 1) {
        int y = __shfl_up_sync(0xFFFFFFFFu, x, o);
        if (lane >= o) x += y;
    }
    __shared__ int ws[8];
    if (lane == 31) ws[wid] = x;
    __syncthreads();
    if (wid == 0 && lane < 8) {
        int w = ws[lane];
        #pragma unroll
        for (int o = 1; o < 8; o <<= 1) {
            int y = __shfl_up_sync(0xFFu, w, o);
            if (lane >= o) w += y;
        }
        ws[lane] = w;
    }
    __syncthreads();

    int blockExcl = ((wid > 0) ? ws[wid - 1] : 0) + (x - s);
    int base = s_base + blockExcl;

    if (idx < N_DIS) {
        int4 o;
        o.x = base;
        o.y = o.x + v.x;
        o.z = o.y + v.y;
        o.w = o.z + v.z;
        *(int4*)&g_off[t][idx] = o;
    }
}

// ---------------- scatter: atomic-free (uses precomputed ranks) --------------
__global__ void scatter_kernel(EdgeIdx ei) {
    int t = blockIdx.y;
    int i = blockIdx.x * blockDim.x + threadIdx.x;
    if (i >= NEDGE) return;
    const float* el_tab[3] = {g_el_ind, g_el_rev, g_el_dd};
    const float* er_tab[3] = {g_er_ind, g_er_rev, g_er_dd};
    int si = ei.src[t][i];
    int di = ei.dst[t][i];
    float e = leaky(el_tab[t][si] + er_tab[t][di]);
    int pos = g_off[t][di] + g_rank[t][i];
    int2 pk;
    pk.x = si;
    pk.y = __float_as_int(e);
    g_edge[t][pos] = pk;
}

// ---------------- per-(dst,etype) softmax + aggregation (warp per task) ------
// smem-staged edge broadcast + packed fma.rn.f32x2 accumulation.
// No max-subtraction: logits bounded (~|e| < 4), exp(e) safe in fp32.
__global__ void __launch_bounds__(256) aggr_kernel(float* __restrict__ h_drug,
                                                   float* __restrict__ h_dis)
{
    __shared__ int2 stage[8][32];

    int gw   = (blockIdx.x * blockDim.x + threadIdx.x) >> 5;
    int wslot = (threadIdx.x >> 5);
    int lane = threadIdx.x & 31;

    int t, d;
    float* outrow;
    if (gw < N_DRUG)               { t = 1; d = gw;                    outrow = h_drug + (size_t)d * DIM; }
    else if (gw < N_DRUG + N_DIS)  { t = 0; d = gw - N_DRUG;           outrow = h_dis  + (size_t)d * DIM; }
    else if (gw < N_DRUG + 2*N_DIS){ t = 2; d = gw - N_DRUG - N_DIS;   outrow = h_dis  + (size_t)d * DIM; }
    else return;

    int lo = g_off[t][d];
    int hi = g_off[t][d + 1];
    int len = hi - lo;
    if (len <= 0) return;

    const __half* __restrict__ Wh = g_Whh[t];

    unsigned long long acc01 = 0ull, acc23 = 0ull;   // packed float2 accumulators

    if (len <= 32) {
        int2 pk = (lane < len) ? g_edge[t][lo + lane]
                               : make_int2(0, 0xFF800000);   // -inf -> exp = 0
        float p = __expf(__int_as_float(pk.y));

        float sm = p;
        #pragma unroll
        for (int o = 16; o > 0; o >>= 1)
            sm += __shfl_xor_sync(0xFFFFFFFFu, sm, o);
        p *= (1.0f / sm);

        stage[wslot][lane] = make_int2(pk.x, __float_as_int(p));
        __syncwarp();

        #pragma unroll 8
        for (int j = 0; j < len; j++) {
            int2 sp = stage[wslot][j];
            float pj = __int_as_float(sp.y);
            unsigned long long pp;
            asm("mov.b64 %0, {%1, %1};" : "=l"(pp) : "f"(pj));
            uint2 u = ((const uint2*)(Wh + (size_t)sp.x * DIM))[lane];
            float2 f0 = __half22float2(*(__half2*)&u.x);
            float2 f1 = __half22float2(*(__half2*)&u.y);
            ffma2(acc01, *(unsigned long long*)&f0, pp);
            ffma2(acc23, *(unsigned long long*)&f1, pp);
        }
    } else {
        float sm = 0.f;
        for (int k = lo + lane; k < hi; k += 32)
            sm += __expf(__int_as_float(g_edge[t][k].y));
        #pragma unroll
        for (int o = 16; o > 0; o >>= 1)
            sm += __shfl_xor_sync(0xFFFFFFFFu, sm, o);
        float inv = 1.0f / sm;

        for (int base = lo; base < hi; base += 32) {
            int n = min(32, hi - base);
            int2 pk = (lane < n) ? g_edge[t][base + lane]
                                 : make_int2(0, 0xFF800000);
            float p = __expf(__int_as_float(pk.y)) * inv;
            stage[wslot][lane] = make_int2(pk.x, __float_as_int(p));
            __syncwarp();

            #pragma unroll 8
            for (int j = 0; j < n; j++) {
                int2 sp = stage[wslot][j];
                float pj = __int_as_float(sp.y);
                unsigned long long pp;
                asm("mov.b64 %0, {%1, %1};" : "=l"(pp) : "f"(pj));
                uint2 u = ((const uint2*)(Wh + (size_t)sp.x * DIM))[lane];
                float2 f0 = __half22float2(*(__half2*)&u.x);
                float2 f1 = __half22float2(*(__half2*)&u.y);
                ffma2(acc01, *(unsigned long long*)&f0, pp);
                ffma2(acc23, *(unsigned long long*)&f1, pp);
            }
            __syncwarp();
        }
    }

    float2 a01 = *(float2*)&acc01;
    float2 a23 = *(float2*)&acc23;
    float4 res = make_float4(a01.x, a01.y, a23.x, a23.y);

    if (t == 1) {
        // h_drug has a single writer -> plain store
        *(float4*)(outrow + lane * 4) = res;
    } else {
        red_add_v4(outrow + lane * 4, res);
    }
}

// ---------------- launch -----------------------------------------------------
extern "C" void kernel_launch(void* const* d_in, const int* in_sizes, int n_in,
                              void* d_out, int out_size)
{
    const float* feat_drug    = (const float*)d_in[0];
    const float* feat_disease = (const float*)d_in[1];
    const float* W_ind = (const float*)d_in[2];
    const float* b_ind = (const float*)d_in[3];
    const float* a_ind = (const float*)d_in[4];
    const float* W_rev = (const float*)d_in[5];
    const float* b_rev = (const float*)d_in[6];
    const float* a_rev = (const float*)d_in[7];
    const float* W_dd  = (const float*)d_in[8];
    const float* b_dd  = (const float*)d_in[9];
    const float* a_dd  = (const float*)d_in[10];
    const int* src_ind = (const int*)d_in[11];
    const int* dst_ind = (const int*)d_in[12];
    const int* src_rev = (const int*)d_in[13];
    const int* dst_rev = (const int*)d_in[14];
    const int* src_dd  = (const int*)d_in[15];
    const int* dst_dd  = (const int*)d_in[16];

    float* out    = (float*)d_out;
    float* h_drug = out;
    float* h_dis  = out + (size_t)N_DRUG * DIM;

    float *el_ind, *er_rev, *el_rev, *er_ind, *el_dd, *er_dd;
    int* degptr;
    cudaGetSymbolAddress((void**)&el_ind, g_el_ind);
    cudaGetSymbolAddress((void**)&er_rev, g_er_rev);
    cudaGetSymbolAddress((void**)&el_rev, g_el_rev);
    cudaGetSymbolAddress((void**)&er_ind, g_er_ind);
    cudaGetSymbolAddress((void**)&el_dd,  g_el_dd);
    cudaGetSymbolAddress((void**)&er_dd,  g_er_dd);
    cudaGetSymbolAddress((void**)&degptr, g_deg);

    cudaStream_t s2;
    cudaStreamCreateWithFlags(&s2, cudaStreamNonBlocking);
    cudaEvent_t ev0, ev2;
    cudaEventCreateWithFlags(&ev0, cudaEventDisableTiming);
    cudaEventCreateWithFlags(&ev2, cudaEventDisableTiming);

    EdgeIdx ei;
    ei.src[0] = src_ind; ei.dst[0] = dst_ind;
    ei.src[1] = src_rev; ei.dst[1] = dst_rev;
    ei.src[2] = src_dd;  ei.dst[2] = dst_dd;

    cudaEventRecord(ev0, 0);
    cudaStreamWaitEvent(s2, ev0, 0);

    // --- side stream: zero out/deg, hist(+rank, MLP4), 2-phase scan ----------
    cudaMemsetAsync(d_out, 0, (size_t)out_size * sizeof(float), s2);
    cudaMemsetAsync(degptr, 0, 3 * N_DIS * sizeof(int), s2);
    dim3 hgrid((NEDGE + 256 * HIST_MLP - 1) / (256 * HIST_MLP), 3);
    hist_kernel<<<hgrid, 256, 0, s2>>>(ei);
    dim3 sgrid(SCAN_NB, 3);
    scan1_kernel<<<sgrid, 256, 0, s2>>>();
    scan3_kernel<<<sgrid, 256, 0, s2>>>();
    cudaEventRecord(ev2, s2);

    // --- main stream: tensor-core GEMM + projections -------------------------
    GemmArgs ga;
    ga.X[0] = feat_drug;    ga.W[0] = W_ind; ga.b[0] = b_ind;
    ga.a1[0] = a_ind;       ga.a2[0] = a_rev + DIM;
    ga.s1[0] = el_ind;      ga.s2[0] = er_rev;

    ga.X[1] = feat_disease; ga.W[1] = W_rev; ga.b[1] = b_rev;
    ga.a1[1] = a_rev;       ga.a2[1] = a_ind + DIM;
    ga.s1[1] = el_rev;      ga.s2[1] = er_ind;

    ga.X[2] = feat_disease; ga.W[2] = W_dd;  ga.b[2] = b_dd;
    ga.a1[2] = a_dd;        ga.a2[2] = a_dd + DIM;
    ga.s1[2] = el_dd;       ga.s2[2] = er_dd;

    dim3 ggrid(GBLKS, 3);
    gemm_wmma_kernel<<<ggrid, 128>>>(ga);

    // --- join, then scatter + aggregation ------------------------------------
    cudaStreamWaitEvent(0, ev2, 0);
    dim3 egrid((NEDGE + 255) / 256, 3);
    scatter_kernel<<<egrid, 256>>>(ei);

    int total_warps = N_DRUG + 2 * N_DIS;
    int ablocks = (total_warps * 32 + 255) / 256;
    aggr_kernel<<<ablocks, 256>>>(h_drug, h_dis);
}

// round 14
// speedup vs baseline: 1.0507x; 1.0507x over previous
#include <cuda_runtime.h>
#include <cuda_fp16.h>
#include <mma.h>
#include <math.h>

using namespace nvcuda;

#define N_DRUG 20000
#define N_DIS  20000
#define NEDGE  300000
#define DIM    128

#define SCAN_ELEMS 1024
#define SCAN_NB    ((N_DIS + SCAN_ELEMS - 1) / SCAN_ELEMS)   // 20
#define OFF_STRIDE (N_DIS + 4)

#define GROWS 64
#define GBLKS ((N_DRUG + GROWS - 1) / GROWS)   // 313

#define HIST_MLP 4

// ---------------- scratch (device globals; no allocation allowed) ----------
__device__ __half g_Whh[3][N_DIS * DIM];     // fp16 Wh per etype (gather source)

__device__ float g_el_ind[N_DRUG];
__device__ float g_er_rev[N_DRUG];
__device__ float g_el_rev[N_DIS];
__device__ float g_er_ind[N_DIS];
__device__ float g_el_dd [N_DIS];
__device__ float g_er_dd [N_DIS];

__device__ int   g_deg[3][N_DIS];            // zero-init; scan3 re-zeros each run
__device__ int   g_off[3][OFF_STRIDE];
__device__ int   g_bsum[3][SCAN_NB];
__device__ int   g_rank[3][NEDGE];           // per-edge rank within its dst
__device__ int2  g_edge[3][NEDGE];           // packed (src, logit-bits), dst-sorted

// ---------------- param structs ---------------------------------------------
struct GemmArgs {
    const float* X[3];
    const float* W[3];
    const float* b[3];
    const float* a1[3];
    const float* a2[3];
    float* s1[3];
    float* s2[3];
};

struct EdgeIdx {
    const int* src[3];
    const int* dst[3];
};

// ---------------- helpers ----------------------------------------------------
__device__ __forceinline__ float leaky(float x) {
    return x > 0.0f ? x : 0.01f * x;
}

// ---------------- WMMA GEMM + bias + attention scalar projections ------------
__global__ void __launch_bounds__(128) gemm_wmma_kernel(GemmArgs ga) {
    const int t = blockIdx.y;
    const int row0 = blockIdx.x * GROWS;
    const float* __restrict__ X  = ga.X[t];
    const float* __restrict__ Wg = ga.W[t];

    __shared__ union {
        struct {
            __half Xs[GROWS][72];
            __half Ws[64][136];
        } mm;
        float ep[GROWS][132];
    } sm;

    int tid  = threadIdx.x;
    int warp = tid >> 5;
    int lane = tid & 31;

    wmma::fragment<wmma::accumulator, 16, 16, 16, float> acc[4][2];
    #pragma unroll
    for (int rt = 0; rt < 4; rt++)
        #pragma unroll
        for (int nf = 0; nf < 2; nf++)
            wmma::fill_fragment(acc[rt][nf], 0.0f);

    for (int chunk = 0; chunk < 2; chunk++) {
        __syncthreads();
        {
            int r  = tid >> 4;
            int cg = (tid & 15) * 4;
            #pragma unroll
            for (int rr = r; rr < GROWS; rr += 8) {
                int grow = row0 + rr;
                float4 x4 = make_float4(0.f, 0.f, 0.f, 0.f);
                if (grow < N_DRUG)
                    x4 = *(const float4*)&X[(size_t)grow * DIM + chunk * 64 + cg];
                *(__half2*)&sm.mm.Xs[rr][cg]     = __floats2half2_rn(x4.x, x4.y);
                *(__half2*)&sm.mm.Xs[rr][cg + 2] = __floats2half2_rn(x4.z, x4.w);
            }
        }
        {
            int r  = tid >> 4;
            int wc = (tid & 15) * 8;
            #pragma unroll
            for (int rr = r; rr < 64; rr += 8) {
                const float* wp = &Wg[(size_t)(chunk * 64 + rr) * DIM + wc];
                float4 f0 = *(const float4*)wp;
                float4 f1 = *(const float4*)(wp + 4);
                __half2 h0 = __floats2half2_rn(f0.x, f0.y);
                __half2 h1 = __floats2half2_rn(f0.z, f0.w);
                __half2 h2 = __floats2half2_rn(f1.x, f1.y);
                __half2 h3 = __floats2half2_rn(f1.z, f1.w);
                uint4 u;
                u.x = *(unsigned*)&h0; u.y = *(unsigned*)&h1;
                u.z = *(unsigned*)&h2; u.w = *(unsigned*)&h3;
                *(uint4*)&sm.mm.Ws[rr][wc] = u;
            }
        }
        __syncthreads();

        #pragma unroll
        for (int k2 = 0; k2 < 4; k2++) {
            wmma::fragment<wmma::matrix_b, 16, 16, 16, __half, wmma::row_major> b0, b1;
            wmma::load_matrix_sync(b0, &sm.mm.Ws[k2 * 16][warp * 32],      136);
            wmma::load_matrix_sync(b1, &sm.mm.Ws[k2 * 16][warp * 32 + 16], 136);
            #pragma unroll
            for (int rt = 0; rt < 4; rt++) {
                wmma::fragment<wmma::matrix_a, 16, 16, 16, __half, wmma::row_major> a;
                wmma::load_matrix_sync(a, &sm.mm.Xs[rt * 16][k2 * 16], 72);
                wmma::mma_sync(acc[rt][0], a, b0, acc[rt][0]);
                wmma::mma_sync(acc[rt][1], a, b1, acc[rt][1]);
            }
        }
    }

    __syncthreads();
    #pragma unroll
    for (int rt = 0; rt < 4; rt++) {
        wmma::store_matrix_sync(&sm.ep[rt * 16][warp * 32],      acc[rt][0], 132,
                                wmma::mem_row_major);
        wmma::store_matrix_sync(&sm.ep[rt * 16][warp * 32 + 16], acc[rt][1], 132,
                                wmma::mem_row_major);
    }
    __syncthreads();

    float4 b4  = *(const float4*)&ga.b[t][lane * 4];
    float4 a14 = *(const float4*)&ga.a1[t][lane * 4];
    float4 a24 = *(const float4*)&ga.a2[t][lane * 4];
    __half* __restrict__ Whh = g_Whh[t];

    #pragma unroll 4
    for (int r = 0; r < 16; r++) {
        int grow = row0 + warp * 16 + r;
        if (grow >= N_DRUG) break;
        float4 v = *(const float4*)&sm.ep[warp * 16 + r][lane * 4];
        v.x += b4.x; v.y += b4.y; v.z += b4.z; v.w += b4.w;

        __half2 h0 = __floats2half2_rn(v.x, v.y);
        __half2 h1 = __floats2half2_rn(v.z, v.w);
        uint2 u;
        u.x = *(unsigned*)&h0;
        u.y = *(unsigned*)&h1;
        *(uint2*)&Whh[(size_t)grow * DIM + lane * 4] = u;

        float p1 = v.x * a14.x + v.y * a14.y + v.z * a14.z + v.w * a14.w;
        float p2 = v.x * a24.x + v.y * a24.y + v.z * a24.z + v.w * a24.w;
        #pragma unroll
        for (int o = 16; o > 0; o >>= 1) {
            p1 += __shfl_down_sync(0xFFFFFFFFu, p1, o);
            p2 += __shfl_down_sync(0xFFFFFFFFu, p2, o);
        }
        if (lane == 0) { ga.s1[t][grow] = p1; ga.s2[t][grow] = p2; }
    }
}

// ---------------- histogram + rank capture, MLP=4 ---------------------------
__global__ void hist_kernel(EdgeIdx ei) {
    int t = blockIdx.y;
    const int* __restrict__ dst = ei.dst[t];
    int stride = gridDim.x * blockDim.x;
    int i0 = blockIdx.x * blockDim.x + threadIdx.x;

    int idx[HIST_MLP], d[HIST_MLP];
    #pragma unroll
    for (int k = 0; k < HIST_MLP; k++) {
        idx[k] = i0 + k * stride;
        d[k]   = (idx[k] < NEDGE) ? dst[idx[k]] : -1;
    }
    int r[HIST_MLP];
    #pragma unroll
    for (int k = 0; k < HIST_MLP; k++)
        if (d[k] >= 0) r[k] = atomicAdd(&g_deg[t][d[k]], 1);
    #pragma unroll
    for (int k = 0; k < HIST_MLP; k++)
        if (d[k] >= 0) g_rank[t][idx[k]] = r[k];
}

// ---------------- scan phase 1: per-block partial sums -----------------------
__global__ void __launch_bounds__(256) scan1_kernel() {
    int t   = blockIdx.y;
    int b   = blockIdx.x;
    int tid = threadIdx.x;
    int idx = b * SCAN_ELEMS + tid * 4;

    int4 v = (idx < N_DIS) ? *(const int4*)&g_deg[t][idx]
                           : make_int4(0, 0, 0, 0);
    int s = v.x + v.y + v.z + v.w;

    int lane = tid & 31, wid = tid >> 5;
    #pragma unroll
    for (int o = 16; o > 0; o >>= 1)
        s += __shfl_down_sync(0xFFFFFFFFu, s, o);

    __shared__ int ws[8];
    if (lane == 0) ws[wid] = s;
    __syncthreads();
    if (tid == 0) {
        int tot = 0;
        #pragma unroll
        for (int i = 0; i < 8; i++) tot += ws[i];
        g_bsum[t][b] = tot;
        if (b == 0) g_off[t][N_DIS] = NEDGE;
    }
}

// ---------------- scan phase 2: final offsets (+ re-zero deg) ----------------
__global__ void __launch_bounds__(256) scan3_kernel() {
    int t   = blockIdx.y;
    int b   = blockIdx.x;
    int tid = threadIdx.x;
    int idx = b * SCAN_ELEMS + tid * 4;
    int lane = tid & 31, wid = tid >> 5;

    __shared__ int s_base;
    if (wid == 0) {
        int v = (lane < b && lane < SCAN_NB) ? g_bsum[t][lane] : 0;
        #pragma unroll
        for (int o = 16; o > 0; o >>= 1)
            v += __shfl_down_sync(0xFFFFFFFFu, v, o);
        if (lane == 0) s_base = v;
    }

    int4 v = (idx < N_DIS) ? *(const int4*)&g_deg[t][idx]
                           : make_int4(0, 0, 0, 0);
    int s = v.x + v.y + v.z + v.w;

    int x = s;
    #pragma unroll
    for (int o = 1; o < 32; o <<= 1) {
        int y = __shfl_up_sync(0xFFFFFFFFu, x, o);
        if (lane >= o) x += y;
    }
    __shared__ int ws[8];
    if (lane == 31) ws[wid] = x;
    __syncthreads();
    if (wid == 0 && lane < 8) {
        int w = ws[lane];
        #pragma unroll
        for (int o = 1; o < 8; o <<= 1) {
            int y = __shfl_up_sync(0xFFu, w, o);
            if (lane >= o) w += y;
        }
        ws[lane] = w;
    }
    __syncthreads();

    int blockExcl = ((wid > 0) ? ws[wid - 1] : 0) + (x - s);
    int base = s_base + blockExcl;

    if (idx < N_DIS) {
        int4 o;
        o.x = base;
        o.y = o.x + v.x;
        o.z = o.y + v.y;
        o.w = o.z + v.z;
        *(int4*)&g_off[t][idx] = o;
        // re-zero deg for the next graph replay (globals are zero-init on load)
        *(int4*)&g_deg[t][idx] = make_int4(0, 0, 0, 0);
    }
}

// ---------------- scatter: atomic-free (uses precomputed ranks) --------------
__global__ void scatter_kernel(EdgeIdx ei) {
    int t = blockIdx.y;
    int i = blockIdx.x * blockDim.x + threadIdx.x;
    if (i >= NEDGE) return;
    const float* el_tab[3] = {g_el_ind, g_el_rev, g_el_dd};
    const float* er_tab[3] = {g_er_ind, g_er_rev, g_er_dd};
    int si = ei.src[t][i];
    int di = ei.dst[t][i];
    float e = leaky(el_tab[t][si] + er_tab[t][di]);
    int pos = g_off[t][di] + g_rank[t][i];
    int2 pk;
    pk.x = si;
    pk.y = __float_as_int(e);
    g_edge[t][pos] = pk;
}

// ---------------- per-dst softmax + aggregation (warp per dst node) ----------
// drug node: etype 1; disease node: etypes 0 + 2 fused -> single plain store.
// No output memset needed; degree-0 rows get explicit zeros.
__device__ __forceinline__ void agg_etype(int t, int d, int lane, float4& acc)
{
    int lo = g_off[t][d];
    int hi = g_off[t][d + 1];
    int len = hi - lo;
    if (len <= 0) return;

    const __half* __restrict__ Wh = g_Whh[t];

    if (len <= 32) {
        int2 pk = (lane < len) ? g_edge[t][lo + lane]
                               : make_int2(0, 0xFF800000);   // -inf -> exp = 0
        float p = __expf(__int_as_float(pk.y));

        float sm = p;
        #pragma unroll
        for (int o = 16; o > 0; o >>= 1)
            sm += __shfl_xor_sync(0xFFFFFFFFu, sm, o);
        p *= (1.0f / sm);

        #pragma unroll 8
        for (int j = 0; j < len; j++) {
            int   sj = __shfl_sync(0xFFFFFFFFu, pk.x, j);
            float pj = __shfl_sync(0xFFFFFFFFu, p, j);
            uint2 u = ((const uint2*)(Wh + (size_t)sj * DIM))[lane];
            float2 f0 = __half22float2(*(__half2*)&u.x);
            float2 f1 = __half22float2(*(__half2*)&u.y);
            acc.x += pj * f0.x;
            acc.y += pj * f0.y;
            acc.z += pj * f1.x;
            acc.w += pj * f1.y;
        }
    } else {
        float sm = 0.f;
        for (int k = lo + lane; k < hi; k += 32)
            sm += __expf(__int_as_float(g_edge[t][k].y));
        #pragma unroll
        for (int o = 16; o > 0; o >>= 1)
            sm += __shfl_xor_sync(0xFFFFFFFFu, sm, o);
        float inv = 1.0f / sm;

        for (int base = lo; base < hi; base += 32) {
            int n = min(32, hi - base);
            int   s = 0;
            float p = 0.f;
            if (lane < n) {
                int2 pk = g_edge[t][base + lane];
                s = pk.x;
                p = __expf(__int_as_float(pk.y)) * inv;
            }
            #pragma unroll 8
            for (int j = 0; j < n; j++) {
                int   sj = __shfl_sync(0xFFFFFFFFu, s, j);
                float pj = __shfl_sync(0xFFFFFFFFu, p, j);
                uint2 u = ((const uint2*)(Wh + (size_t)sj * DIM))[lane];
                float2 f0 = __half22float2(*(__half2*)&u.x);
                float2 f1 = __half22float2(*(__half2*)&u.y);
                acc.x += pj * f0.x;
                acc.y += pj * f0.y;
                acc.z += pj * f1.x;
                acc.w += pj * f1.y;
            }
        }
    }
}

__global__ void __launch_bounds__(256) aggr_kernel(float* __restrict__ h_drug,
                                                   float* __restrict__ h_dis)
{
    int gw   = (blockIdx.x * blockDim.x + threadIdx.x) >> 5;
    int lane = threadIdx.x & 31;
    if (gw >= N_DRUG + N_DIS) return;

    float4 acc = make_float4(0.f, 0.f, 0.f, 0.f);

    if (gw < N_DRUG) {
        agg_etype(1, gw, lane, acc);
        *(float4*)(h_drug + (size_t)gw * DIM + lane * 4) = acc;
    } else {
        int d = gw - N_DRUG;
        agg_etype(0, d, lane, acc);
        agg_etype(2, d, lane, acc);
        *(float4*)(h_dis + (size_t)d * DIM + lane * 4) = acc;
    }
}

// ---------------- launch -----------------------------------------------------
extern "C" void kernel_launch(void* const* d_in, const int* in_sizes, int n_in,
                              void* d_out, int out_size)
{
    const float* feat_drug    = (const float*)d_in[0];
    const float* feat_disease = (const float*)d_in[1];
    const float* W_ind = (const float*)d_in[2];
    const float* b_ind = (const float*)d_in[3];
    const float* a_ind = (const float*)d_in[4];
    const float* W_rev = (const float*)d_in[5];
    const float* b_rev = (const float*)d_in[6];
    const float* a_rev = (const float*)d_in[7];
    const float* W_dd  = (const float*)d_in[8];
    const float* b_dd  = (const float*)d_in[9];
    const float* a_dd  = (const float*)d_in[10];
    const int* src_ind = (const int*)d_in[11];
    const int* dst_ind = (const int*)d_in[12];
    const int* src_rev = (const int*)d_in[13];
    const int* dst_rev = (const int*)d_in[14];
    const int* src_dd  = (const int*)d_in[15];
    const int* dst_dd  = (const int*)d_in[16];

    float* out    = (float*)d_out;
    float* h_drug = out;
    float* h_dis  = out + (size_t)N_DRUG * DIM;

    float *el_ind, *er_rev, *el_rev, *er_ind, *el_dd, *er_dd;
    cudaGetSymbolAddress((void**)&el_ind, g_el_ind);
    cudaGetSymbolAddress((void**)&er_rev, g_er_rev);
    cudaGetSymbolAddress((void**)&el_rev, g_el_rev);
    cudaGetSymbolAddress((void**)&er_ind, g_er_ind);
    cudaGetSymbolAddress((void**)&el_dd,  g_el_dd);
    cudaGetSymbolAddress((void**)&er_dd,  g_er_dd);

    cudaStream_t s2;
    cudaStreamCreateWithFlags(&s2, cudaStreamNonBlocking);
    cudaEvent_t ev0, ev2;
    cudaEventCreateWithFlags(&ev0, cudaEventDisableTiming);
    cudaEventCreateWithFlags(&ev2, cudaEventDisableTiming);

    EdgeIdx ei;
    ei.src[0] = src_ind; ei.dst[0] = dst_ind;
    ei.src[1] = src_rev; ei.dst[1] = dst_rev;
    ei.src[2] = src_dd;  ei.dst[2] = dst_dd;

    cudaEventRecord(ev0, 0);
    cudaStreamWaitEvent(s2, ev0, 0);

    // --- side stream: hist(+rank, MLP4), 2-phase scan (scan3 re-zeros deg) ---
    dim3 hgrid((NEDGE + 256 * HIST_MLP - 1) / (256 * HIST_MLP), 3);
    hist_kernel<<<hgrid, 256, 0, s2>>>(ei);
    dim3 sgrid(SCAN_NB, 3);
    scan1_kernel<<<sgrid, 256, 0, s2>>>();
    scan3_kernel<<<sgrid, 256, 0, s2>>>();
    cudaEventRecord(ev2, s2);

    // --- main stream: tensor-core GEMM + projections -------------------------
    GemmArgs ga;
    ga.X[0] = feat_drug;    ga.W[0] = W_ind; ga.b[0] = b_ind;
    ga.a1[0] = a_ind;       ga.a2[0] = a_rev + DIM;
    ga.s1[0] = el_ind;      ga.s2[0] = er_rev;

    ga.X[1] = feat_disease; ga.W[1] = W_rev; ga.b[1] = b_rev;
    ga.a1[1] = a_rev;       ga.a2[1] = a_ind + DIM;
    ga.s1[1] = el_rev;      ga.s2[1] = er_ind;

    ga.X[2] = feat_disease; ga.W[2] = W_dd;  ga.b[2] = b_dd;
    ga.a1[2] = a_dd;        ga.a2[2] = a_dd + DIM;
    ga.s1[2] = el_dd;       ga.s2[2] = er_dd;

    dim3 ggrid(GBLKS, 3);
    gemm_wmma_kernel<<<ggrid, 128>>>(ga);

    // --- join, then scatter + aggregation ------------------------------------
    cudaStreamWaitEvent(0, ev2, 0);
    dim3 egrid((NEDGE + 255) / 256, 3);
    scatter_kernel<<<egrid, 256>>>(ei);

    int total_warps = N_DRUG + N_DIS;
    int ablocks = (total_warps * 32 + 255) / 256;
    aggr_kernel<<<ablocks, 256>>>(h_drug, h_dis);
}